// round 15
// baseline (speedup 1.0000x reference)
#include <cuda_runtime.h>
#include <cuda_fp16.h>
#include <cstdint>

#define N_IN     256
#define DDEG     8
#define N_OUT    64
#define M_TILE   256
#define N_CHUNKS 32

#define SMA(p)   ((p) * 32768)
#define SMB(p)   (65536 + (p) * 8192)
#define SM_TOTAL 81920

#define ASWZ3(fr, c, ks) ((((fr) + 2 * (c) + 4 * (((ks) >> 1) & 1)) & 7) + 8 * (c))

__device__ __half g_Bpack[N_CHUNKS * 4096];

__global__ void repack_kernel(const float* __restrict__ c_basis) {
    int idx = blockIdx.x * 256 + threadIdx.x;
    int e    = idx & 7;
    int lane = (idx >> 3) & 31;
    int ng   = (idx >> 8) & 3;
    int ks   = (idx >> 10) & 3;
    int ch   = idx >> 12;
    int nt = ng * 2 + (e >> 2);
    int bp = (e >> 1) & 1;
    int h  = e & 1;
    int k  = ks * 16 + bp * 8 + (lane & 3) * 2 + h;
    int n  = nt * 8 + (lane >> 2);
    int kg = ch * 64 + k;
    int i = kg >> 3, d = kg & 7;
    g_Bpack[idx] = __float2half_rn(c_basis[(n * N_IN + i) * DDEG + d]);
}

#define MMA16816(ac, A0, A1, A2, A3, B0, B1)                                  \
    asm volatile(                                                             \
        "mma.sync.aligned.m16n8k16.row.col.f32.f16.f16.f32 "                  \
        "{%0,%1,%2,%3}, {%4,%5,%6,%7}, {%8,%9}, {%0,%1,%2,%3};"               \
        : "+f"((ac)[0]), "+f"((ac)[1]), "+f"((ac)[2]), "+f"((ac)[3])          \
        : "r"(A0), "r"(A1), "r"(A2), "r"(A3), "r"(B0), "r"(B1))

__device__ __forceinline__ void cp_async16(uint32_t saddr, const void* gptr) {
    asm volatile("cp.async.ca.shared.global [%0], [%1], 16;"
                 :: "r"(saddr), "l"(gptr) : "memory");
}

// Math half of gen: tanh + Legendre for 4 feats -> 16 packed half2 regs.
__device__ __forceinline__ void gen_math(float4 xv, uint32_t hp[16]) {
    float xf[4] = {xv.x, xv.y, xv.z, xv.w};
    #pragma unroll
    for (int f = 0; f < 4; f++) {
        float e2 = __expf(2.0f * xf[f]);
        float t  = 1.0f - __fdividef(2.0f, e2 + 1.0f);
        float pv[8];
        pv[0] = t;
        float pp = 1.0f, pc = t;
        #pragma unroll
        for (int d = 1; d < 8; d++) {
            float kk = (float)(d + 1);
            float a_ = (2.0f * kk - 1.0f) / kk;
            float b_ = (kk - 1.0f) / kk;
            float pn = a_ * t * pc - b_ * pp;
            pv[d] = pn; pp = pc; pc = pn;
        }
        #pragma unroll
        for (int cc = 0; cc < 4; cc++) {
            __half2 h2 = __floats2half2_rn(pv[2 * cc], pv[2 * cc + 1]);
            hp[f * 4 + cc] = *(uint32_t*)&h2;
        }
    }
}

// Store half of gen: 8 STS.64 at loop-invariant offsets.
__device__ __forceinline__ void gen_sts(char* Ab, const uint32_t hp[16],
                                        const uint32_t gsts[4]) {
    #pragma unroll
    for (int p2 = 0; p2 < 2; p2++)
        #pragma unroll
        for (int cc = 0; cc < 4; cc++)
            *(uint2*)(Ab + gsts[cc] + p2 * 8192) =
                make_uint2(hp[(p2 * 2) * 4 + cc], hp[(p2 * 2 + 1) * 4 + cc]);
}

__device__ __forceinline__ void mma_chunk(float (&acc)[2][8][4],
                                          const char* ArL, const char* ArH,
                                          const char* Br) {
    #pragma unroll
    for (int ks = 0; ks < 4; ks++) {
        const char* Ar = (ks < 2) ? ArL : ArH;
        uint4 a0 = *(const uint4*)(Ar + ks * 8192);
        uint4 a1 = *(const uint4*)(Ar + ks * 8192 + 512);
        uint4 bq[4];
        #pragma unroll
        for (int q = 0; q < 4; q++)
            bq[q] = *(const uint4*)(Br + (ks * 4 + q) * 512);
        const uint32_t* bp = (const uint32_t*)bq;
        if (ks < 2) {
            #pragma unroll
            for (int nt = 0; nt < 8; nt++) {
                MMA16816(acc[0][nt], a0.x, a0.z, a0.y, a0.w, bp[2 * nt], bp[2 * nt + 1]);
                MMA16816(acc[1][nt], a1.x, a1.z, a1.y, a1.w, bp[2 * nt], bp[2 * nt + 1]);
            }
        } else {
            #pragma unroll
            for (int nt = 0; nt < 8; nt++) {
                MMA16816(acc[0][nt], a0.z, a0.x, a0.w, a0.y, bp[2 * nt], bp[2 * nt + 1]);
                MMA16816(acc[1][nt], a1.z, a1.x, a1.w, a1.y, bp[2 * nt], bp[2 * nt + 1]);
            }
        }
    }
}

extern __shared__ __align__(128) char sm[];

__global__ __launch_bounds__(256, 2)
void kan_fp16_kernel(const float* __restrict__ x, const float* __restrict__ bias,
                     float* __restrict__ y, int batch) {
    const int tid  = threadIdx.x;
    const int lane = tid & 31;
    const int wid  = tid >> 5;
    const int wm   = wid;
    const int rowBase = blockIdx.x * M_TILE;
    const uint32_t sbase = (uint32_t)__cvta_generic_to_shared(sm);

    const int grow = tid >> 1;
    const int half = tid & 1;
    const int mt_g = grow >> 4;
    const int rh_g = (grow >> 3) & 1;
    const int fr_g = grow & 7;
    int rg0 = rowBase + grow;        if (rg0 > batch - 1) rg0 = batch - 1;
    int rg1 = rowBase + grow + 128;  if (rg1 > batch - 1) rg1 = batch - 1;
    const float* xrow0 = x + (size_t)rg0 * N_IN + half * 4;   // pass-0 rows
    const float* xrow1 = x + (size_t)rg1 * N_IN + half * 4;   // pass-1 rows
    const int sh_g = (rh_g ^ half) * 8;

    uint32_t gsts[4];
    {
        int ks0 = half * 2;
        #pragma unroll
        for (int cc = 0; cc < 4; cc++)
            gsts[cc] = (uint32_t)((ks0 * 16 + mt_g) * 512
                                  + ASWZ3(fr_g, cc, ks0) * 16 + sh_g);
    }

    const int c  = lane & 3;
    const int fr = lane >> 2;
    const uint32_t aoffL = (uint32_t)(wm * 1024 + ASWZ3(fr, c, 0) * 16);
    const uint32_t aoffH = (uint32_t)(wm * 1024 + ASWZ3(fr, c, 2) * 16);
    const uint32_t boff  = (uint32_t)(lane * 16);

    float acc[2][8][4] = {};
    uint32_t hp0[16];                          // carried pass-0 values

    // ---- prolog: stage B(0); math0(0); prefetch x ----
    {
        const char* src = (const char*)g_Bpack;
        cp_async16(sbase + SMB(0) + tid * 16,         src + tid * 16);
        cp_async16(sbase + SMB(0) + (tid + 256) * 16, src + (tid + 256) * 16);
        asm volatile("cp.async.commit_group;" ::: "memory");
    }
    float4 xv0 = *(const float4*)xrow0;        // pass-0, chunk 0
    float4 xv1 = *(const float4*)xrow1;        // pass-1, chunk 0
    gen_math(xv0, hp0);                        // pass-0 math for chunk 0
    xv0 = *(const float4*)(xrow0 + 8);         // pass-0, chunk 1

    #pragma unroll 1
    for (int ch = 0; ch < N_CHUNKS; ch += 2) {
        // ============ sub-iteration P = 0 (chunk ch) ============
        {
            char* Ab = sm + SMA(0);
            gen_sts(Ab, hp0, gsts);                       // pass-0 STS (carried)
            {
                uint32_t hp1[16];
                gen_math(xv1, hp1);                       // pass-1 full
                gen_sts(Ab + 4096, hp1, gsts);
            }
            xv1 = *(const float4*)(xrow1 + (ch + 1) * 8); // always valid (ch<=30)

            asm volatile("cp.async.wait_group 0;" ::: "memory");
            __syncthreads();

            const char* src = (const char*)g_Bpack + (size_t)(ch + 1) * 8192;
            cp_async16(sbase + SMB(1) + tid * 16,         src + tid * 16);
            cp_async16(sbase + SMB(1) + (tid + 256) * 16, src + (tid + 256) * 16);
            asm volatile("cp.async.commit_group;" ::: "memory");

            gen_math(xv0, hp0);                           // pass-0 math for ch+1,
            if (ch + 2 < N_CHUNKS)                        // overlaps MMA below
                xv0 = *(const float4*)(xrow0 + (ch + 2) * 8);

            mma_chunk(acc, sm + SMA(0) + aoffL, sm + SMA(0) + aoffH,
                      sm + SMB(0) + boff);
        }
        // ============ sub-iteration P = 1 (chunk ch+1) ============
        {
            char* Ab = sm + SMA(1);
            gen_sts(Ab, hp0, gsts);
            {
                uint32_t hp1[16];
                gen_math(xv1, hp1);
                gen_sts(Ab + 4096, hp1, gsts);
            }
            if (ch + 2 < N_CHUNKS)
                xv1 = *(const float4*)(xrow1 + (ch + 2) * 8);

            asm volatile("cp.async.wait_group 0;" ::: "memory");
            __syncthreads();

            if (ch + 2 < N_CHUNKS) {
                const char* src = (const char*)g_Bpack + (size_t)(ch + 2) * 8192;
                cp_async16(sbase + SMB(0) + tid * 16,         src + tid * 16);
                cp_async16(sbase + SMB(0) + (tid + 256) * 16, src + (tid + 256) * 16);
                asm volatile("cp.async.commit_group;" ::: "memory");

                gen_math(xv0, hp0);                       // pass-0 math for ch+2
                if (ch + 3 < N_CHUNKS)
                    xv0 = *(const float4*)(xrow0 + (ch + 3) * 8);
            }

            mma_chunk(acc, sm + SMA(1) + aoffL, sm + SMA(1) + aoffH,
                      sm + SMB(1) + boff);
        }
    }

    // ---- epilogue: bias + store ----
    #pragma unroll
    for (int t = 0; t < 2; t++) {
        int r0 = rowBase + wm * 32 + t * 16 + fr;
        #pragma unroll
        for (int nt = 0; nt < 8; nt++) {
            int col = nt * 8 + c * 2;
            float2 bb = *(const float2*)(bias + col);
            if (r0 < batch)
                *(float2*)(y + (size_t)r0 * N_OUT + col) =
                    make_float2(acc[t][nt][0] + bb.x, acc[t][nt][1] + bb.y);
            if (r0 + 8 < batch)
                *(float2*)(y + (size_t)(r0 + 8) * N_OUT + col) =
                    make_float2(acc[t][nt][2] + bb.x, acc[t][nt][3] + bb.y);
        }
    }
}

extern "C" void kernel_launch(void* const* d_in, const int* in_sizes, int n_in,
                              void* d_out, int out_size) {
    const float* x       = (const float*)d_in[0];
    const float* c_basis = (const float*)d_in[1];
    const float* bias    = (const float*)d_in[2];
    float* y = (float*)d_out;
    int batch = in_sizes[0] / N_IN;

    cudaFuncSetAttribute(kan_fp16_kernel,
                         cudaFuncAttributeMaxDynamicSharedMemorySize, SM_TOTAL);

    repack_kernel<<<(N_CHUNKS * 4096) / 256, 256>>>(c_basis);
    int grid = (batch + M_TILE - 1) / M_TILE;
    kan_fp16_kernel<<<grid, 256, SM_TOTAL>>>(x, bias, y, batch);
}

// round 16
// speedup vs baseline: 1.0308x; 1.0308x over previous
#include <cuda_runtime.h>
#include <cuda_fp16.h>
#include <cstdint>

#define N_IN     256
#define DDEG     8
#define N_OUT    64
#define M_TILE   256
#define N_CHUNKS 32

// smem byte offsets: A double-buffered 32KB each (256 rows x 64 k fp16),
// B double-buffered 8KB each
#define SMA(p)   ((p) * 32768)
#define SMB(p)   (65536 + (p) * 8192)
#define SM_TOTAL 81920

// A-tile in-block swizzle: slot for (fr, c) within a (ks, mtile) 512B block.
// Conflict-free for gen STS.64 phases and consumer LDS.128 phases (round-8 proof;
// block bases are multiples of 512B so bank patterns are block-invariant).
#define ASWZ3(fr, c, ks) ((((fr) + 2 * (c) + 4 * (((ks) >> 1) & 1)) & 7) + 8 * (c))

// B prepacked as exact per-chunk smem fragment images: 32 chunks x 4096 halves
__device__ __half g_Bpack[N_CHUNKS * 4096];

// Layout: [ch][ks(4)][ng(4)][lane(32)][e(8 halves)]; uint4 slot = frags of
// n-tiles {2ng, 2ng+1}: {nt0.b01, nt0.b23, nt1.b01, nt1.b23}
__global__ void repack_kernel(const float* __restrict__ c_basis) {
    int idx = blockIdx.x * 256 + threadIdx.x;          // 131072 total
    int e    = idx & 7;
    int lane = (idx >> 3) & 31;
    int ng   = (idx >> 8) & 3;
    int ks   = (idx >> 10) & 3;
    int ch   = idx >> 12;
    int nt = ng * 2 + (e >> 2);
    int bp = (e >> 1) & 1;                             // b01 vs b23 (k +8)
    int h  = e & 1;
    int k  = ks * 16 + bp * 8 + (lane & 3) * 2 + h;    // k within chunk
    int n  = nt * 8 + (lane >> 2);
    int kg = ch * 64 + k;
    int i = kg >> 3, d = kg & 7;
    g_Bpack[idx] = __float2half_rn(c_basis[(n * N_IN + i) * DDEG + d]);
}

#define MMA16816(ac, A0, A1, A2, A3, B0, B1)                                  \
    asm volatile(                                                             \
        "mma.sync.aligned.m16n8k16.row.col.f32.f16.f16.f32 "                  \
        "{%0,%1,%2,%3}, {%4,%5,%6,%7}, {%8,%9}, {%0,%1,%2,%3};"               \
        : "+f"((ac)[0]), "+f"((ac)[1]), "+f"((ac)[2]), "+f"((ac)[3])          \
        : "r"(A0), "r"(A1), "r"(A2), "r"(A3), "r"(B0), "r"(B1))

__device__ __forceinline__ void cp_async16(uint32_t saddr, const void* gptr) {
    asm volatile("cp.async.ca.shared.global [%0], [%1], 16;"
                 :: "r"(saddr), "l"(gptr) : "memory");
}

// Generate one (row, 4 feats) quartet of Legendre values into A-slots:
// 8 STS.64, conflict-free (byte-half sh_g = (rh ^ half)*8).
__device__ __forceinline__ void gen_tile(char* Ab, float4 xv,
                                         int mt_g, int fr_g, int half, int sh_g) {
    float xf[4] = {xv.x, xv.y, xv.z, xv.w};
    uint32_t hp[4][4];                         // [feat][c-pair] half2 bits
    #pragma unroll
    for (int f = 0; f < 4; f++) {
        float e2 = __expf(2.0f * xf[f]);
        float t  = 1.0f - __fdividef(2.0f, e2 + 1.0f);
        float pv[8];
        pv[0] = t;
        float pp = 1.0f, pc = t;
        #pragma unroll
        for (int d = 1; d < 8; d++) {
            float kk = (float)(d + 1);
            float a_ = (2.0f * kk - 1.0f) / kk;
            float b_ = (kk - 1.0f) / kk;
            float pn = a_ * t * pc - b_ * pp;
            pv[d] = pn; pp = pc; pc = pn;
        }
        #pragma unroll
        for (int cc = 0; cc < 4; cc++) {
            __half2 h2 = __floats2half2_rn(pv[2 * cc], pv[2 * cc + 1]);
            hp[f][cc] = *(uint32_t*)&h2;
        }
    }
    #pragma unroll
    for (int p2 = 0; p2 < 2; p2++) {
        int ks = half * 2 + p2;
        char* blk = Ab + (ks * 16 + mt_g) * 512 + sh_g;   // 16 m-tiles per ks
        #pragma unroll
        for (int cc = 0; cc < 4; cc++) {
            uint2 v = make_uint2(hp[p2 * 2][cc], hp[p2 * 2 + 1][cc]);
            *(uint2*)(blk + ASWZ3(fr_g, cc, ks) * 16) = v;
        }
    }
}

extern __shared__ __align__(128) char sm[];

__global__ __launch_bounds__(256, 2)
void kan_fp16_kernel(const float* __restrict__ x, const float* __restrict__ bias,
                     float* __restrict__ y, int batch) {
    const int tid  = threadIdx.x;
    const int lane = tid & 31;
    const int wid  = tid >> 5;
    const int wm   = wid;              // warp = m32 group (rows wm*32..+31), all 64 cols
    const int rowBase = blockIdx.x * M_TILE;
    const uint32_t sbase = (uint32_t)__cvta_generic_to_shared(sm);

    // ---- gen mapping: adjacent lanes = two feat-halves of the SAME row;
    // each thread covers rows {grow, grow+128} (two passes) ----
    const int grow = tid >> 1;                   // 0..127
    const int half = tid & 1;                    // feats half*4 .. half*4+3
    const int mt_g = grow >> 4;                  // m-tile 0..7 (pass 0); +8 pass 1
    const int rh_g = (grow >> 3) & 1;
    const int fr_g = grow & 7;
    int rg0 = rowBase + grow;        if (rg0 > batch - 1) rg0 = batch - 1;
    int rg1 = rowBase + grow + 128;  if (rg1 > batch - 1) rg1 = batch - 1;
    const float* xrow0 = x + (size_t)rg0 * N_IN + half * 4;
    const float* xrow1 = x + (size_t)rg1 * N_IN + half * 4;
    const int sh_g = (rh_g ^ half) * 8;

    // ---- consumer fragment indices ----
    const int c  = lane & 3;
    const int fr = lane >> 2;

    float acc[2][8][4] = {};

    // ---- prolog: cp.async stage B(0), prefetch x(0) ----
    {
        const char* src = (const char*)g_Bpack;
        cp_async16(sbase + SMB(0) + tid * 16,         src + tid * 16);
        cp_async16(sbase + SMB(0) + (tid + 256) * 16, src + (tid + 256) * 16);
        asm volatile("cp.async.commit_group;" ::: "memory");
    }
    float4 xv0 = *(const float4*)xrow0;
    float4 xv1 = *(const float4*)xrow1;

    for (int ch = 0; ch < N_CHUNKS; ch++) {
        const int p = ch & 1;

        // ---- generate A(ch): two row-passes, swizzled fragment layout ----
        {
            char* Ab = sm + SMA(p);
            float4 xa = xv0, xb = xv1;
            if (ch + 1 < N_CHUNKS) {
                xv0 = *(const float4*)(xrow0 + (ch + 1) * 8);
                xv1 = *(const float4*)(xrow1 + (ch + 1) * 8);
            }
            gen_tile(Ab, xa, mt_g,     fr_g, half, sh_g);
            gen_tile(Ab, xb, mt_g + 8, fr_g, half, sh_g);
        }

        // ---- B(ch) arrived + A(ch) visible ----
        asm volatile("cp.async.wait_group 0;" ::: "memory");
        __syncthreads();

        // ---- prefetch B(ch+1) (safe: all warps finished MMA(ch-1)) ----
        if (ch + 1 < N_CHUNKS) {
            const char* src = (const char*)g_Bpack + (size_t)(ch + 1) * 8192;
            cp_async16(sbase + SMB(p ^ 1) + tid * 16,         src + tid * 16);
            cp_async16(sbase + SMB(p ^ 1) + (tid + 256) * 16, src + (tid + 256) * 16);
            asm volatile("cp.async.commit_group;" ::: "memory");
        }

        // ---- MMA(ch): 4 k-steps x (2 m-tiles x 8 n-tiles) m16n8k16 ----
        // ks<2: slot = (rl.i0, rl.i1, rh.i0, rh.i1) -> A order (x,z,y,w)
        // ks>=2: byte-halves swapped -> A order (z,x,w,y)
        {
            const char* Ar = sm + SMA(p);
            const char* Br = sm + SMB(p);
            #pragma unroll
            for (int ks = 0; ks < 4; ks++) {
                uint4 a0 = *(const uint4*)(Ar + (ks * 16 + wm * 2 + 0) * 512 + ASWZ3(fr, c, ks) * 16);
                uint4 a1 = *(const uint4*)(Ar + (ks * 16 + wm * 2 + 1) * 512 + ASWZ3(fr, c, ks) * 16);
                uint4 bq[4];
                #pragma unroll
                for (int q = 0; q < 4; q++)
                    bq[q] = *(const uint4*)(Br + ((ks * 4 + q) * 32 + lane) * 16);
                const uint32_t* bp = (const uint32_t*)bq;
                if (ks < 2) {
                    #pragma unroll
                    for (int nt = 0; nt < 8; nt++) {
                        MMA16816(acc[0][nt], a0.x, a0.z, a0.y, a0.w, bp[2 * nt], bp[2 * nt + 1]);
                        MMA16816(acc[1][nt], a1.x, a1.z, a1.y, a1.w, bp[2 * nt], bp[2 * nt + 1]);
                    }
                } else {
                    #pragma unroll
                    for (int nt = 0; nt < 8; nt++) {
                        MMA16816(acc[0][nt], a0.z, a0.x, a0.w, a0.y, bp[2 * nt], bp[2 * nt + 1]);
                        MMA16816(acc[1][nt], a1.z, a1.x, a1.w, a1.y, bp[2 * nt], bp[2 * nt + 1]);
                    }
                }
            }
        }
    }

    // ---- epilogue: bias + store (warp covers rows wm*32..+31, all 64 cols) ----
    #pragma unroll
    for (int t = 0; t < 2; t++) {
        int r0 = rowBase + wm * 32 + t * 16 + fr;
        #pragma unroll
        for (int nt = 0; nt < 8; nt++) {
            int col = nt * 8 + c * 2;
            float2 bb = *(const float2*)(bias + col);
            if (r0 < batch)
                *(float2*)(y + (size_t)r0 * N_OUT + col) =
                    make_float2(acc[t][nt][0] + bb.x, acc[t][nt][1] + bb.y);
            if (r0 + 8 < batch)
                *(float2*)(y + (size_t)(r0 + 8) * N_OUT + col) =
                    make_float2(acc[t][nt][2] + bb.x, acc[t][nt][3] + bb.y);
        }
    }
}

extern "C" void kernel_launch(void* const* d_in, const int* in_sizes, int n_in,
                              void* d_out, int out_size) {
    const float* x       = (const float*)d_in[0];
    const float* c_basis = (const float*)d_in[1];
    const float* bias    = (const float*)d_in[2];
    float* y = (float*)d_out;
    int batch = in_sizes[0] / N_IN;

    cudaFuncSetAttribute(kan_fp16_kernel,
                         cudaFuncAttributeMaxDynamicSharedMemorySize, SM_TOTAL);

    repack_kernel<<<(N_CHUNKS * 4096) / 256, 256>>>(c_basis);
    int grid = (batch + M_TILE - 1) / M_TILE;
    kan_fp16_kernel<<<grid, 256, SM_TOTAL>>>(x, bias, y, batch);
}